// round 12
// baseline (speedup 1.0000x reference)
#include <cuda_runtime.h>
#include <cuda_bf16.h>
#include <cstdint>
#include <math.h>

#define B_ROWS 4096
#define N_ROWS 8192
#define D_DIM  256
#define TILE_BYTES 65536     // 128 rows x 256 bf16 (pre-swizzled)
#define SUBK_BYTES 16384     // 128 rows x 64 bf16 sub-tile
#define HALF_BYTES 32768     // 128 rows x 128 K (half tile)
#define IDESC_F16 0x8200490u // f32 acc, bf16 a/b, M=128, N=128
#define THREADS 576          // 16 epilogue warps + 1 MMA warp + 1 TMA warp
#define NEPI 16              // epilogue warps

// ---- smem layout (dynamic) ----
#define SMEM_A    0                    // 2 A tiles, 131072 B
#define SMEM_B    131072               // 3 half-tile slots x 32768 = 98304
#define SMEM_CTRL 229376               // tmem ptr (4B)
#define SMEM_MBAR (SMEM_CTRL + 16)     // 9 barriers x 8B
// reduction scratch ALIASES the B ring (only used after the mainloop)
#define SMEM_SRED SMEM_B               // 1024 floats (4 chunks x 256)
#define SMEM_TOTAL (SMEM_CTRL + 128)   // 229504 < 227KB limit

// barriers: [0]=a_full  [1..3]=b_full[slot]  [4..6]=hdone[slot]  [7..8]=d_free[p]
#define BAR(i) (smem_base + SMEM_MBAR + 8 * (i))

// Arch-specific gate: tcgen05 is an 'a'-feature; the family-portable
// compute_103 gencode pass must see NO tcgen05 PTX.
#if defined(__CUDA_ARCH__) && \
    (defined(__CUDA_ARCH_FEAT_SM103_ALL) || \
     (defined(__CUDA_ARCH_SPECIFIC__) && (__CUDA_ARCH_SPECIFIC__ == 1030)))
#define TC_ENABLED 1
#else
#define TC_ENABLED 0
#endif

// ---- device globals (no allocation allowed) ----
__device__ __align__(16) unsigned char g_zswz[N_ROWS * D_DIM * 2]; // 4MB bf16, pre-swizzled
__device__ float g_ps[4][N_ROWS];   // per-j-quarter exp-sum partials
__device__ float g_posd[N_ROWS];
__device__ unsigned int g_ctr = 0;

// ---------------- arch-neutral PTX helpers (sm_90 baseline) ----------------
__device__ __forceinline__ uint32_t smem_u32(const void* p) {
    uint32_t a;
    asm("{ .reg .u64 t; cvta.to.shared.u64 t, %1; cvt.u32.u64 %0, t; }" : "=r"(a) : "l"(p));
    return a;
}
#define MBARRIER_INIT(addr, cnt) \
    asm volatile("mbarrier.init.shared.b64 [%0], %1;" :: "r"(addr), "r"((uint32_t)(cnt)) : "memory")
#define MBARRIER_EXPECT_TX(addr, bytes) \
    asm volatile("mbarrier.arrive.expect_tx.shared.b64 _, [%0], %1;" :: "r"(addr), "r"((uint32_t)(bytes)) : "memory")
#define MBARRIER_ARRIVE(addr) \
    asm volatile("mbarrier.arrive.shared.b64 _, [%0];" :: "r"(addr) : "memory")
#define MBARRIER_WAIT_PARITY(addr, par) do {                                   \
    uint32_t _m = (addr), _p = (uint32_t)(par), _done;                          \
    asm volatile("{\n\t.reg .pred p;\n\t"                                       \
        "mbarrier.try_wait.parity.acquire.cta.shared::cta.b64 p, [%1], %2;\n\t" \
        "selp.b32 %0, 1, 0, p;\n\t}" : "=r"(_done) : "r"(_m), "r"(_p) : "memory"); \
    if (!_done) {                                                               \
        asm volatile("{\n\t.reg .pred P1;\n\t"                                  \
            "WL_%=:\n\t"                                                        \
            "mbarrier.try_wait.parity.acquire.cta.shared::cta.b64 P1, [%0], %1, 0x989680;\n\t" \
            "@P1 bra.uni WD_%=;\n\t"                                            \
            "bra.uni WL_%=;\n\t"                                                \
            "WD_%=:\n\t}" :: "r"(_m), "r"(_p) : "memory");                      \
    } } while (0)

__device__ __forceinline__ void bulk_copy(uint32_t dst_smem, const void* src, uint32_t bytes, uint32_t mbar) {
    asm volatile("cp.async.bulk.shared::cluster.global.mbarrier::complete_tx::bytes [%0], [%1], %2, [%3];"
        :: "r"(dst_smem), "l"(src), "r"(bytes), "r"(mbar) : "memory");
}
__device__ __forceinline__ float fast_ex2(float x) {
    float y; asm("ex2.approx.f32 %0, %1;" : "=f"(y) : "f"(x)); return y;
}
__device__ __forceinline__ float fast_lg2(float x) {
    float y; asm("lg2.approx.f32 %0, %1;" : "=f"(y) : "f"(x)); return y;
}
__device__ __forceinline__ uint32_t swz128(uint32_t x) { return x ^ ((x >> 3) & 0x70); }

// ---------------- tcgen05 helpers (sm_103a only) ----------------
#if TC_ENABLED
#define TCGEN05_ALLOC(sm, n) \
    asm volatile("tcgen05.alloc.cta_group::1.sync.aligned.shared::cta.b32 [%0], %1;" :: "r"(sm), "r"((uint32_t)(n)) : "memory")
#define TCGEN05_DEALLOC(t, n) \
    asm volatile("tcgen05.dealloc.cta_group::1.sync.aligned.b32 %0, %1;" :: "r"(t), "r"((uint32_t)(n)))
#define TCGEN05_RELINQ() \
    asm volatile("tcgen05.relinquish_alloc_permit.cta_group::1.sync.aligned;")
#define TCGEN05_COMMIT(mb) \
    asm volatile("tcgen05.commit.cta_group::1.mbarrier::arrive::one.shared::cluster.b64 [%0];" :: "r"(mb) : "memory")
#define TCGEN05_WAIT_LD()  asm volatile("tcgen05.wait::ld.sync.aligned;" ::: "memory")
#define TCGEN05_FENCE_BEFORE() asm volatile("tcgen05.fence::before_thread_sync;" ::: "memory")
#define TCGEN05_FENCE_AFTER()  asm volatile("tcgen05.fence::after_thread_sync;" ::: "memory")

#define TCGEN05_LD_X32(r, a) \
    asm volatile("tcgen05.ld.sync.aligned.32x32b.x32.b32 " \
        "{%0,%1,%2,%3,%4,%5,%6,%7,%8,%9,%10,%11,%12,%13,%14,%15," \
        "%16,%17,%18,%19,%20,%21,%22,%23,%24,%25,%26,%27,%28,%29,%30,%31}, [%32];" \
        : "=r"((r)[0]),"=r"((r)[1]),"=r"((r)[2]),"=r"((r)[3]),"=r"((r)[4]),"=r"((r)[5]),"=r"((r)[6]),"=r"((r)[7]), \
          "=r"((r)[8]),"=r"((r)[9]),"=r"((r)[10]),"=r"((r)[11]),"=r"((r)[12]),"=r"((r)[13]),"=r"((r)[14]),"=r"((r)[15]), \
          "=r"((r)[16]),"=r"((r)[17]),"=r"((r)[18]),"=r"((r)[19]),"=r"((r)[20]),"=r"((r)[21]),"=r"((r)[22]),"=r"((r)[23]), \
          "=r"((r)[24]),"=r"((r)[25]),"=r"((r)[26]),"=r"((r)[27]),"=r"((r)[28]),"=r"((r)[29]),"=r"((r)[30]),"=r"((r)[31]) \
        : "r"(a))

// SW128 descriptor: layout=2 (SW128), version=1, SBO=64, LBO=1
__device__ __forceinline__ uint64_t make_desc(uint32_t addr) {
    uint64_t base = (uint64_t(2) << 61) | (uint64_t(1) << 46) | (uint64_t(64) << 32) | (uint64_t(1) << 16);
    return base | ((uint64_t)(addr >> 4) & 0x3FFF);
}
__device__ __forceinline__ void mma_f16_ss(uint32_t d, uint64_t ad, uint64_t bd, uint32_t idesc, bool en) {
    uint32_t e = en ? 1u : 0u;
    asm volatile("{\n\t.reg .pred p;\n\tsetp.ne.u32 p, %5, 0;\n\t"
        "tcgen05.mma.cta_group::1.kind::f16 [%0], %1, %2, %3, {%4,%4,%4,%4}, p;\n\t}"
        :: "r"(d), "l"(ad), "l"(bd), "r"(idesc), "r"(0u), "r"(e) : "memory");
}

// Issue the 16 MMAs for half-of-tile H (K-half hk over both A tiles). MMA warp only.
__device__ __forceinline__ void issue_half(int H, uint32_t smem_base, uint32_t tmem_base) {
    const int slot = H % 3, rnd = H / 3;
    const int l = H >> 1, hk = H & 1, p = l & 1;
    MBARRIER_WAIT_PARITY(BAR(1 + slot), rnd & 1);          // B half delivered
    if (hk == 0 && l >= 2)
        MBARRIER_WAIT_PARITY(BAR(7 + p), ((l >> 1) - 1) & 1); // D pair free
    TCGEN05_FENCE_AFTER();
    const uint32_t bbase = smem_base + SMEM_B + slot * HALF_BYTES;
    #pragma unroll
    for (int a = 0; a < 2; ++a) {
        const uint32_t abase = smem_base + SMEM_A + a * TILE_BYTES + hk * HALF_BYTES;
        const uint32_t dt = tmem_base + (p * 2 + a) * 128;
        #pragma unroll
        for (int kcl = 0; kcl < 2; ++kcl)
            #pragma unroll
            for (int q = 0; q < 4; ++q)
                mma_f16_ss(dt,
                           make_desc(abase + kcl * SUBK_BYTES) + q * 2,
                           make_desc(bbase + kcl * SUBK_BYTES) + q * 2,
                           IDESC_F16, !(hk == 0 && kcl == 0 && q == 0));
    }
    TCGEN05_COMMIT(BAR(4 + slot));
}

// TMA one B half-tile into ring slot. TMA warp only.
__device__ __forceinline__ void produce_half(int H, int q, uint32_t smem_base) {
    const int slot = H % 3, rnd = H / 3;
    if (rnd >= 1) MBARRIER_WAIT_PARITY(BAR(4 + slot), (rnd - 1) & 1); // MMA done with slot
    MBARRIER_EXPECT_TX(BAR(1 + slot), HALF_BYTES);
    bulk_copy(smem_base + SMEM_B + slot * HALF_BYTES,
              g_zswz + (size_t)(q * 16 + (H >> 1)) * TILE_BYTES + (size_t)(H & 1) * HALF_BYTES,
              HALF_BYTES, BAR(1 + slot));
}

// process 32 TMEM f32 values: e = exp2(2*log2e*(d-1)); accumulate
// MODE: 0 = plain, 1 = diagonal region (mask j==i), 2 = positive region (capture d)
template<int MODE>
__device__ __forceinline__ void proc32(const uint32_t* dv, int cb, int rrow, int gi,
                                       float* a) {
    const float C1 = 2.8853900817779268f;   // 2*log2(e)
    #pragma unroll
    for (int k = 0; k < 32; ++k) {
        float d = __uint_as_float(dv[k]);
        float e = fast_ex2(fmaf(d, C1, -C1));
        if (MODE == 1) { if (cb + k == rrow) e = 0.f; }
        if (MODE == 2) { if (cb + k == rrow) g_posd[gi] = d; }
        a[k & 3] += e;
    }
}

// Per-tile epilogue over BOTH 128-row regions, 32 cols per warp.
// Both regions loaded with single x32 LDTMs issued back-to-back -> ONE wait,
// then the D pair is freed IMMEDIATELY (data is in registers) so the next
// MMA overlaps with this tile's MUFU math.
template<int M0, int M1>
__device__ __forceinline__ void epi_tile(uint32_t t0, uint32_t t1, int cb, int rrow,
                                         int gi0, int gi1, uint32_t dfree_bar, int lane,
                                         float (&acc)[2][4]) {
    uint32_t dv0[32], dv1[32];
    TCGEN05_LD_X32(dv0, t0);
    TCGEN05_LD_X32(dv1, t1);
    TCGEN05_WAIT_LD();
    TCGEN05_FENCE_BEFORE();
    if (lane == 0) MBARRIER_ARRIVE(dfree_bar);      // D pair free: values in regs
    proc32<M0>(dv0, cb, rrow, gi0, acc[0]);
    proc32<M1>(dv1, cb, rrow, gi1, acc[1]);
}
#endif // TC_ENABLED

// ---------------------------------------------------------------------------
// Kernel 1: normalize rows, bf16-convert, store PRE-SWIZZLED tile layout.
// Two rows per warp for 2x memory-level parallelism (latency-bound kernel).
// ---------------------------------------------------------------------------
__global__ void prep_kernel(const float* __restrict__ zi, const float* __restrict__ zj) {
    int warp = (blockIdx.x * blockDim.x + threadIdx.x) >> 5;  // 0..4095
    int lane = threadIdx.x & 31;
    int r0 = warp * 2;
    if (r0 >= N_ROWS) return;
    const float* base = (r0 < B_ROWS) ? zi : (zj - (size_t)B_ROWS * D_DIM);
    const float4* sA = (const float4*)(base + (size_t)r0 * D_DIM);
    const float4* sB = (const float4*)(base + (size_t)(r0 + 1) * D_DIM);
    float4 a0 = sA[lane * 2], a1 = sA[lane * 2 + 1];
    float4 b0 = sB[lane * 2], b1 = sB[lane * 2 + 1];

    float ssA = a0.x*a0.x + a0.y*a0.y + a0.z*a0.z + a0.w*a0.w
              + a1.x*a1.x + a1.y*a1.y + a1.z*a1.z + a1.w*a1.w;
    float ssB = b0.x*b0.x + b0.y*b0.y + b0.z*b0.z + b0.w*b0.w
              + b1.x*b1.x + b1.y*b1.y + b1.z*b1.z + b1.w*b1.w;
    #pragma unroll
    for (int o = 16; o; o >>= 1) {
        ssA += __shfl_xor_sync(0xffffffffu, ssA, o);
        ssB += __shfl_xor_sync(0xffffffffu, ssB, o);
    }
    float invA = 1.0f / fmaxf(sqrtf(ssA), 1e-12f);
    float invB = 1.0f / fmaxf(sqrtf(ssB), 1e-12f);

    __nv_bfloat162 pa0 = __floats2bfloat162_rn(a0.x*invA, a0.y*invA);
    __nv_bfloat162 pa1 = __floats2bfloat162_rn(a0.z*invA, a0.w*invA);
    __nv_bfloat162 pa2 = __floats2bfloat162_rn(a1.x*invA, a1.y*invA);
    __nv_bfloat162 pa3 = __floats2bfloat162_rn(a1.z*invA, a1.w*invA);
    __nv_bfloat162 pb0 = __floats2bfloat162_rn(b0.x*invB, b0.y*invB);
    __nv_bfloat162 pb1 = __floats2bfloat162_rn(b0.z*invB, b0.w*invB);
    __nv_bfloat162 pb2 = __floats2bfloat162_rn(b1.x*invB, b1.y*invB);
    __nv_bfloat162 pb3 = __floats2bfloat162_rn(b1.z*invB, b1.w*invB);
    uint4 uA, uB;
    uA.x = *reinterpret_cast<uint32_t*>(&pa0); uA.y = *reinterpret_cast<uint32_t*>(&pa1);
    uA.z = *reinterpret_cast<uint32_t*>(&pa2); uA.w = *reinterpret_cast<uint32_t*>(&pa3);
    uB.x = *reinterpret_cast<uint32_t*>(&pb0); uB.y = *reinterpret_cast<uint32_t*>(&pb1);
    uB.z = *reinterpret_cast<uint32_t*>(&pb2); uB.w = *reinterpret_cast<uint32_t*>(&pb3);

    int kc = lane >> 3;                          // K 64-chunk
    uint32_t col = (uint32_t)((lane & 7) * 16);
    int t = r0 >> 7;
    int rA = r0 & 127, rB = (r0 + 1) & 127;      // same tile (rows are a pair)
    *reinterpret_cast<uint4*>(g_zswz + (size_t)t * TILE_BYTES + kc * SUBK_BYTES
                              + swz128((uint32_t)(rA * 128) + col)) = uA;
    *reinterpret_cast<uint4*>(g_zswz + (size_t)t * TILE_BYTES + kc * SUBK_BYTES
                              + swz128((uint32_t)(rB * 128) + col)) = uB;
}

// ---------------------------------------------------------------------------
// Kernel 2: warp-specialized tcgen05 GEMM, M=256 per CTA, j-quarter per CTA,
// fused fixed-max exp-sum epilogue + last-CTA final loss reduction.
// Warps 0-15: epilogue (4 per TMEM subpartition x 4 column chunks of 32;
// each region chunk loaded as one x32 LDTM; single wait per tile).
// Warp 16: MMA issuer. Warp 17: TMA producer.
// Grid 128: mm = bid & 31 (rows 256*mm..), q = bid >> 5 (j tiles q*16..+15).
// ---------------------------------------------------------------------------
__global__ __launch_bounds__(THREADS, 1) void gemm_lse_kernel(float* __restrict__ out) {
#if TC_ENABLED
    extern __shared__ char smem[];
    const uint32_t smem_base = smem_u32(smem);
    const int tid  = threadIdx.x;
    const int wid  = tid >> 5;
    const int lane = tid & 31;
    const int mm   = blockIdx.x & 31;
    const int q    = blockIdx.x >> 5;
    const int NT   = 16;                        // j tiles per CTA

    if (wid == 0) TCGEN05_ALLOC(smem_base + SMEM_CTRL, 512);
    if (tid == 0) {
        MBARRIER_INIT(BAR(0), 1);                                   // a_full
        MBARRIER_INIT(BAR(1), 1); MBARRIER_INIT(BAR(2), 1); MBARRIER_INIT(BAR(3), 1); // b_full
        MBARRIER_INIT(BAR(4), 1); MBARRIER_INIT(BAR(5), 1); MBARRIER_INIT(BAR(6), 1); // hdone
        MBARRIER_INIT(BAR(7), NEPI); MBARRIER_INIT(BAR(8), NEPI);   // d_free (16 warps)
    }
    __syncthreads();
    uint32_t tmem_base;
    asm volatile("ld.shared.b32 %0, [%1];" : "=r"(tmem_base) : "r"(smem_base + SMEM_CTRL));

    if (tid == 17 * 32) {
        // ---- TMA producer warp ----
        MBARRIER_EXPECT_TX(BAR(0), 2 * TILE_BYTES);
        bulk_copy(smem_base + SMEM_A, g_zswz + (size_t)(2 * mm) * TILE_BYTES,
                  2 * TILE_BYTES, BAR(0));
        for (int H = 0; H < 2 * NT; ++H) produce_half(H, q, smem_base);
    }
    if (tid == 16 * 32) {
        // ---- MMA issuer warp ----
        MBARRIER_WAIT_PARITY(BAR(0), 0);        // A resident
        for (int H = 0; H < 2 * NT; ++H) issue_half(H, smem_base, tmem_base);
    }

    // ---- epilogue warps (0-15) ----
    const int sub     = wid & 3;                // TMEM subpartition (lane group)
    const int chunk   = wid >> 2;               // 32-col chunk (0..3)
    const int rrow    = sub * 32 + lane;
    const int colbase = chunk * 32;
    const int gbase   = mm * 256;
    float acc[2][4] = {{0.f,0.f,0.f,0.f},{0.f,0.f,0.f,0.f}};

    if (wid < NEPI) {
        const int tA0 = 2 * mm, tA1 = 2 * mm + 1;
        const int pA0 = tA0 ^ 32, pA1 = tA1 ^ 32;
        const int gi0 = gbase + rrow, gi1 = gbase + 128 + rrow;
        for (int l = 0; l < NT; ++l) {
            const int p = l & 1;
            const int jt = q * 16 + l;

            // wait for tile l's MMAs (hdone of its second half)
            const int H2 = 2 * l + 1;
            MBARRIER_WAIT_PARITY(BAR(4 + H2 % 3), (H2 / 3) & 1);
            TCGEN05_FENCE_AFTER();

            const uint32_t t0 = tmem_base + (p * 2) * 128 + colbase
                              + ((uint32_t)sub << 21);
            const uint32_t t1 = t0 + 128;
            const uint32_t db = BAR(7 + p);

            if (jt == tA0)      epi_tile<1,0>(t0, t1, colbase, rrow, gi0, gi1, db, lane, acc);
            else if (jt == tA1) epi_tile<0,1>(t0, t1, colbase, rrow, gi0, gi1, db, lane, acc);
            else if (jt == pA0) epi_tile<2,0>(t0, t1, colbase, rrow, gi0, gi1, db, lane, acc);
            else if (jt == pA1) epi_tile<0,2>(t0, t1, colbase, rrow, gi0, gi1, db, lane, acc);
            else                epi_tile<0,0>(t0, t1, colbase, rrow, gi0, gi1, db, lane, acc);
        }
    }

    // --- combine per-chunk partials per row, store ---
    // (sred aliases the B ring; all B consumption finished before this point)
    __syncthreads();
    float* sred = reinterpret_cast<float*>(smem + SMEM_SRED);
    if (wid < NEPI) {
        sred[chunk * 256 + 0   + rrow] = (acc[0][0] + acc[0][1]) + (acc[0][2] + acc[0][3]);
        sred[chunk * 256 + 128 + rrow] = (acc[1][0] + acc[1][1]) + (acc[1][2] + acc[1][3]);
    }
    __syncthreads();
    if (tid < 256) g_ps[q][gbase + tid] =
        (sred[tid] + sred[256 + tid]) + (sred[512 + tid] + sred[768 + tid]);

    __syncthreads();
    if (wid == 0) { TCGEN05_RELINQ(); TCGEN05_DEALLOC(tmem_base, 512); }

    // --- last-CTA final reduction: loss_i = 2 + ln(S_i) - 2*posd_i; mean ---
    __shared__ unsigned int s_last;
    if (tid == 0) {
        __threadfence();                         // release all this CTA's writes
        s_last = (atomicAdd(&g_ctr, 1u) == 127u) ? 1u : 0u;
    }
    __syncthreads();
    if (s_last) {
        __threadfence();                         // acquire other CTAs' writes
        const float LN2 = 0.6931471805599453f;
        if (tid < 256) {
            float s = 0.0f;
            for (int i = tid; i < N_ROWS; i += 256) {
                float S = (__ldcg(&g_ps[0][i]) + __ldcg(&g_ps[1][i]))
                        + (__ldcg(&g_ps[2][i]) + __ldcg(&g_ps[3][i]));
                s += fmaf(fast_lg2(S), LN2, 2.0f - 2.0f * __ldcg(&g_posd[i]));
            }
            sred[tid] = s;
        }
        __syncthreads();
        #pragma unroll
        for (int o = 128; o; o >>= 1) {
            if (tid < o) sred[tid] += sred[tid + o];
            __syncthreads();
        }
        if (tid == 0) {
            out[0] = sred[0] / (float)N_ROWS;
            g_ctr = 0u;                          // reset for next graph replay
        }
    }
#endif // TC_ENABLED
}

// ---------------------------------------------------------------------------
extern "C" void kernel_launch(void* const* d_in, const int* in_sizes, int n_in,
                              void* d_out, int out_size) {
    const float* zi = (const float*)d_in[0];
    const float* zj = (const float*)d_in[1];
    float* out = (float*)d_out;

    cudaFuncSetAttribute(gemm_lse_kernel,
                         cudaFuncAttributeMaxDynamicSharedMemorySize, SMEM_TOTAL);

    prep_kernel<<<512, 256>>>(zi, zj);
    gemm_lse_kernel<<<128, THREADS, SMEM_TOTAL>>>(out);
}

// round 13
// speedup vs baseline: 1.2065x; 1.2065x over previous
#include <cuda_runtime.h>
#include <cuda_fp16.h>
#include <cstdint>
#include <math.h>

#define B_ROWS 4096
#define N_ROWS 8192
#define D_DIM  256
#define TILE_BYTES 65536     // 128 rows x 256 f16 (pre-swizzled)
#define SUBK_BYTES 16384     // 128 rows x 64 f16 sub-tile
#define HALF_BYTES 32768     // 128 rows x 128 K (half tile)
#define IDESC_HF 0x08200000u // f16 acc, f16 a/b, M=128, N=128
#define THREADS 576          // 16 epilogue warps + 1 MMA warp + 1 TMA warp
#define NEPI 16              // epilogue warps

// ---- smem layout (dynamic) ----
#define SMEM_A    0                    // 2 A tiles, 131072 B
#define SMEM_B    131072               // 3 half-tile slots x 32768 = 98304
#define SMEM_CTRL 229376               // tmem ptr (4B)
#define SMEM_MBAR (SMEM_CTRL + 16)     // 9 barriers x 8B
// reduction scratch ALIASES the B ring (only used after the mainloop)
#define SMEM_SRED SMEM_B               // 1024 floats (4 chunks x 256)
#define SMEM_TOTAL (SMEM_CTRL + 128)   // 229504 < 227KB limit

// barriers: [0]=a_full  [1..3]=b_full[slot]  [4..6]=hdone[slot]  [7..8]=d_free[p]
#define BAR(i) (smem_base + SMEM_MBAR + 8 * (i))

// Arch-specific gate: tcgen05 is an 'a'-feature; the family-portable
// compute_103 gencode pass must see NO tcgen05 PTX.
#if defined(__CUDA_ARCH__) && \
    (defined(__CUDA_ARCH_FEAT_SM103_ALL) || \
     (defined(__CUDA_ARCH_SPECIFIC__) && (__CUDA_ARCH_SPECIFIC__ == 1030)))
#define TC_ENABLED 1
#else
#define TC_ENABLED 0
#endif

// ---- device globals (no allocation allowed) ----
__device__ __align__(16) unsigned char g_zswz[N_ROWS * D_DIM * 2]; // 4MB f16, pre-swizzled
__device__ float g_ps[4][N_ROWS];   // per-j-quarter exp-sum partials
__device__ float g_posd[N_ROWS];
__device__ unsigned int g_ctr = 0;

// ---------------- arch-neutral PTX helpers (sm_90 baseline) ----------------
__device__ __forceinline__ uint32_t smem_u32(const void* p) {
    uint32_t a;
    asm("{ .reg .u64 t; cvta.to.shared.u64 t, %1; cvt.u32.u64 %0, t; }" : "=r"(a) : "l"(p));
    return a;
}
#define MBARRIER_INIT(addr, cnt) \
    asm volatile("mbarrier.init.shared.b64 [%0], %1;" :: "r"(addr), "r"((uint32_t)(cnt)) : "memory")
#define MBARRIER_EXPECT_TX(addr, bytes) \
    asm volatile("mbarrier.arrive.expect_tx.shared.b64 _, [%0], %1;" :: "r"(addr), "r"((uint32_t)(bytes)) : "memory")
#define MBARRIER_ARRIVE(addr) \
    asm volatile("mbarrier.arrive.shared.b64 _, [%0];" :: "r"(addr) : "memory")
#define MBARRIER_WAIT_PARITY(addr, par) do {                                   \
    uint32_t _m = (addr), _p = (uint32_t)(par), _done;                          \
    asm volatile("{\n\t.reg .pred p;\n\t"                                       \
        "mbarrier.try_wait.parity.acquire.cta.shared::cta.b64 p, [%1], %2;\n\t" \
        "selp.b32 %0, 1, 0, p;\n\t}" : "=r"(_done) : "r"(_m), "r"(_p) : "memory"); \
    if (!_done) {                                                               \
        asm volatile("{\n\t.reg .pred P1;\n\t"                                  \
            "WL_%=:\n\t"                                                        \
            "mbarrier.try_wait.parity.acquire.cta.shared::cta.b64 P1, [%0], %1, 0x989680;\n\t" \
            "@P1 bra.uni WD_%=;\n\t"                                            \
            "bra.uni WL_%=;\n\t"                                                \
            "WD_%=:\n\t}" :: "r"(_m), "r"(_p) : "memory");                      \
    } } while (0)

__device__ __forceinline__ void bulk_copy(uint32_t dst_smem, const void* src, uint32_t bytes, uint32_t mbar) {
    asm volatile("cp.async.bulk.shared::cluster.global.mbarrier::complete_tx::bytes [%0], [%1], %2, [%3];"
        :: "r"(dst_smem), "l"(src), "r"(bytes), "r"(mbar) : "memory");
}
__device__ __forceinline__ float fast_lg2(float x) {
    float y; asm("lg2.approx.f32 %0, %1;" : "=f"(y) : "f"(x)); return y;
}
__device__ __forceinline__ uint32_t swz128(uint32_t x) { return x ^ ((x >> 3) & 0x70); }

// ---------------- tcgen05 helpers (sm_103a only) ----------------
#if TC_ENABLED
#define TCGEN05_ALLOC(sm, n) \
    asm volatile("tcgen05.alloc.cta_group::1.sync.aligned.shared::cta.b32 [%0], %1;" :: "r"(sm), "r"((uint32_t)(n)) : "memory")
#define TCGEN05_DEALLOC(t, n) \
    asm volatile("tcgen05.dealloc.cta_group::1.sync.aligned.b32 %0, %1;" :: "r"(t), "r"((uint32_t)(n)))
#define TCGEN05_RELINQ() \
    asm volatile("tcgen05.relinquish_alloc_permit.cta_group::1.sync.aligned;")
#define TCGEN05_COMMIT(mb) \
    asm volatile("tcgen05.commit.cta_group::1.mbarrier::arrive::one.shared::cluster.b64 [%0];" :: "r"(mb) : "memory")
#define TCGEN05_WAIT_LD()  asm volatile("tcgen05.wait::ld.sync.aligned;" ::: "memory")
#define TCGEN05_FENCE_BEFORE() asm volatile("tcgen05.fence::before_thread_sync;" ::: "memory")
#define TCGEN05_FENCE_AFTER()  asm volatile("tcgen05.fence::after_thread_sync;" ::: "memory")

#define TCGEN05_LD_X16(r, a) \
    asm volatile("tcgen05.ld.sync.aligned.32x32b.x16.b32 " \
        "{%0,%1,%2,%3,%4,%5,%6,%7,%8,%9,%10,%11,%12,%13,%14,%15}, [%16];" \
        : "=r"((r)[0]),"=r"((r)[1]),"=r"((r)[2]),"=r"((r)[3]),"=r"((r)[4]),"=r"((r)[5]),"=r"((r)[6]),"=r"((r)[7]), \
          "=r"((r)[8]),"=r"((r)[9]),"=r"((r)[10]),"=r"((r)[11]),"=r"((r)[12]),"=r"((r)[13]),"=r"((r)[14]),"=r"((r)[15]) \
        : "r"(a))

// SW128 descriptor: layout=2 (SW128), version=1, SBO=64, LBO=1
__device__ __forceinline__ uint64_t make_desc(uint32_t addr) {
    uint64_t base = (uint64_t(2) << 61) | (uint64_t(1) << 46) | (uint64_t(64) << 32) | (uint64_t(1) << 16);
    return base | ((uint64_t)(addr >> 4) & 0x3FFF);
}
__device__ __forceinline__ void mma_f16_ss(uint32_t d, uint64_t ad, uint64_t bd, uint32_t idesc, bool en) {
    uint32_t e = en ? 1u : 0u;
    asm volatile("{\n\t.reg .pred p;\n\tsetp.ne.u32 p, %5, 0;\n\t"
        "tcgen05.mma.cta_group::1.kind::f16 [%0], %1, %2, %3, {%4,%4,%4,%4}, p;\n\t}"
        :: "r"(d), "l"(ad), "l"(bd), "r"(idesc), "r"(0u), "r"(e) : "memory");
}

// Issue the 16 MMAs for half-of-tile H (K-half hk over both A tiles). MMA warp only.
// D is f16: each 128-col region spans 64 TMEM words.
__device__ __forceinline__ void issue_half(int H, uint32_t smem_base, uint32_t tmem_base) {
    const int slot = H % 3, rnd = H / 3;
    const int l = H >> 1, hk = H & 1, p = l & 1;
    MBARRIER_WAIT_PARITY(BAR(1 + slot), rnd & 1);          // B half delivered
    if (hk == 0 && l >= 2)
        MBARRIER_WAIT_PARITY(BAR(7 + p), ((l >> 1) - 1) & 1); // D pair free
    TCGEN05_FENCE_AFTER();
    const uint32_t bbase = smem_base + SMEM_B + slot * HALF_BYTES;
    #pragma unroll
    for (int a = 0; a < 2; ++a) {
        const uint32_t abase = smem_base + SMEM_A + a * TILE_BYTES + hk * HALF_BYTES;
        const uint32_t dt = tmem_base + (p * 2 + a) * 64;   // f16 D: 64 words/region
        #pragma unroll
        for (int kcl = 0; kcl < 2; ++kcl)
            #pragma unroll
            for (int q = 0; q < 4; ++q)
                mma_f16_ss(dt,
                           make_desc(abase + kcl * SUBK_BYTES) + q * 2,
                           make_desc(bbase + kcl * SUBK_BYTES) + q * 2,
                           IDESC_HF, !(hk == 0 && kcl == 0 && q == 0));
    }
    TCGEN05_COMMIT(BAR(4 + slot));
}

// TMA one B half-tile into ring slot. TMA warp only.
__device__ __forceinline__ void produce_half(int H, int q, uint32_t smem_base) {
    const int slot = H % 3, rnd = H / 3;
    if (rnd >= 1) MBARRIER_WAIT_PARITY(BAR(4 + slot), (rnd - 1) & 1); // MMA done with slot
    MBARRIER_EXPECT_TX(BAR(1 + slot), HALF_BYTES);
    bulk_copy(smem_base + SMEM_B + slot * HALF_BYTES,
              g_zswz + (size_t)(q * 16 + (H >> 1)) * TILE_BYTES + (size_t)(H & 1) * HALF_BYTES,
              HALF_BYTES, BAR(1 + slot));
}

// process 16 f16x2 TMEM words (32 cols): e = exp2(C1*(d-1)), C1 = 2*log2(e).
// One ex2.approx.f16x2 per TWO columns; intra-tile sums in f16x2 (<=4 terms),
// converted to f32 at the end. Word k = cols cb+2k (lo), cb+2k+1 (hi).
// MODE: 0 = plain, 1 = diagonal region (mask j==i), 2 = positive region (capture d)
template<int MODE>
__device__ __forceinline__ void proc16h(const uint32_t* dv, int cb, int rrow, int gi,
                                        float* facc) {
    const __half2 C1h  = __float2half2_rn(2.8853900817779268f);
    const __half2 nC1h = __float2half2_rn(-2.8853900817779268f);
    __half2 hacc[4];
    hacc[0] = hacc[1] = hacc[2] = hacc[3] = __float2half2_rn(0.f);
    #pragma unroll
    for (int k = 0; k < 16; ++k) {
        __half2 d2 = *reinterpret_cast<const __half2*>(&dv[k]);
        if (MODE == 2) {
            if (cb + 2 * k     == rrow) g_posd[gi] = __low2float(d2);
            if (cb + 2 * k + 1 == rrow) g_posd[gi] = __high2float(d2);
        }
        __half2 arg = __hfma2(d2, C1h, nC1h);
        uint32_t eb;
        asm("ex2.approx.f16x2 %0, %1;" : "=r"(eb)
            : "r"(*reinterpret_cast<uint32_t*>(&arg)));
        if (MODE == 1) {
            if (cb + 2 * k     == rrow) eb &= 0xFFFF0000u;  // zero lo half
            if (cb + 2 * k + 1 == rrow) eb &= 0x0000FFFFu;  // zero hi half
        }
        hacc[k & 3] = __hadd2(hacc[k & 3], *reinterpret_cast<__half2*>(&eb));
    }
    #pragma unroll
    for (int i = 0; i < 4; ++i) {
        float2 f = __half22float2(hacc[i]);
        facc[i] += f.x + f.y;
    }
}

// Per-tile epilogue over BOTH 128-row regions, 32 cols per warp.
// f16 D: 2 x16 loads (one per region), ONE wait, D pair freed immediately.
template<int M0, int M1>
__device__ __forceinline__ void epi_tile(uint32_t t0, uint32_t t1, int cb, int rrow,
                                         int gi0, int gi1, uint32_t dfree_bar, int lane,
                                         float (&acc)[2][4]) {
    uint32_t dv0[16], dv1[16];
    TCGEN05_LD_X16(dv0, t0);
    TCGEN05_LD_X16(dv1, t1);
    TCGEN05_WAIT_LD();
    TCGEN05_FENCE_BEFORE();
    if (lane == 0) MBARRIER_ARRIVE(dfree_bar);      // D pair free: values in regs
    proc16h<M0>(dv0, cb, rrow, gi0, acc[0]);
    proc16h<M1>(dv1, cb, rrow, gi1, acc[1]);
}
#endif // TC_ENABLED

// ---------------------------------------------------------------------------
// Kernel 1: normalize rows, f16-convert, store PRE-SWIZZLED tile layout.
// Two rows per warp for 2x memory-level parallelism (latency-bound kernel).
// ---------------------------------------------------------------------------
__global__ void prep_kernel(const float* __restrict__ zi, const float* __restrict__ zj) {
    int warp = (blockIdx.x * blockDim.x + threadIdx.x) >> 5;  // 0..4095
    int lane = threadIdx.x & 31;
    int r0 = warp * 2;
    if (r0 >= N_ROWS) return;
    const float* base = (r0 < B_ROWS) ? zi : (zj - (size_t)B_ROWS * D_DIM);
    const float4* sA = (const float4*)(base + (size_t)r0 * D_DIM);
    const float4* sB = (const float4*)(base + (size_t)(r0 + 1) * D_DIM);
    float4 a0 = sA[lane * 2], a1 = sA[lane * 2 + 1];
    float4 b0 = sB[lane * 2], b1 = sB[lane * 2 + 1];

    float ssA = a0.x*a0.x + a0.y*a0.y + a0.z*a0.z + a0.w*a0.w
              + a1.x*a1.x + a1.y*a1.y + a1.z*a1.z + a1.w*a1.w;
    float ssB = b0.x*b0.x + b0.y*b0.y + b0.z*b0.z + b0.w*b0.w
              + b1.x*b1.x + b1.y*b1.y + b1.z*b1.z + b1.w*b1.w;
    #pragma unroll
    for (int o = 16; o; o >>= 1) {
        ssA += __shfl_xor_sync(0xffffffffu, ssA, o);
        ssB += __shfl_xor_sync(0xffffffffu, ssB, o);
    }
    float invA = 1.0f / fmaxf(sqrtf(ssA), 1e-12f);
    float invB = 1.0f / fmaxf(sqrtf(ssB), 1e-12f);

    __half2 pa0 = __floats2half2_rn(a0.x*invA, a0.y*invA);
    __half2 pa1 = __floats2half2_rn(a0.z*invA, a0.w*invA);
    __half2 pa2 = __floats2half2_rn(a1.x*invA, a1.y*invA);
    __half2 pa3 = __floats2half2_rn(a1.z*invA, a1.w*invA);
    __half2 pb0 = __floats2half2_rn(b0.x*invB, b0.y*invB);
    __half2 pb1 = __floats2half2_rn(b0.z*invB, b0.w*invB);
    __half2 pb2 = __floats2half2_rn(b1.x*invB, b1.y*invB);
    __half2 pb3 = __floats2half2_rn(b1.z*invB, b1.w*invB);
    uint4 uA, uB;
    uA.x = *reinterpret_cast<uint32_t*>(&pa0); uA.y = *reinterpret_cast<uint32_t*>(&pa1);
    uA.z = *reinterpret_cast<uint32_t*>(&pa2); uA.w = *reinterpret_cast<uint32_t*>(&pa3);
    uB.x = *reinterpret_cast<uint32_t*>(&pb0); uB.y = *reinterpret_cast<uint32_t*>(&pb1);
    uB.z = *reinterpret_cast<uint32_t*>(&pb2); uB.w = *reinterpret_cast<uint32_t*>(&pb3);

    int kc = lane >> 3;                          // K 64-chunk
    uint32_t col = (uint32_t)((lane & 7) * 16);
    int t = r0 >> 7;
    int rA = r0 & 127, rB = (r0 + 1) & 127;      // same tile (rows are a pair)
    *reinterpret_cast<uint4*>(g_zswz + (size_t)t * TILE_BYTES + kc * SUBK_BYTES
                              + swz128((uint32_t)(rA * 128) + col)) = uA;
    *reinterpret_cast<uint4*>(g_zswz + (size_t)t * TILE_BYTES + kc * SUBK_BYTES
                              + swz128((uint32_t)(rB * 128) + col)) = uB;
}

// ---------------------------------------------------------------------------
// Kernel 2: warp-specialized tcgen05 GEMM (f16 in, f16 accumulators), M=256
// per CTA, j-quarter per CTA, fused exp-sum epilogue + last-CTA reduction.
// Warps 0-15: epilogue (4 per TMEM subpartition x 4 column chunks of 32).
// Warp 16: MMA issuer. Warp 17: TMA producer.
// Grid 128: mm = bid & 31 (rows 256*mm..), q = bid >> 5 (j tiles q*16..+15).
// ---------------------------------------------------------------------------
__global__ __launch_bounds__(THREADS, 1) void gemm_lse_kernel(float* __restrict__ out) {
#if TC_ENABLED
    extern __shared__ char smem[];
    const uint32_t smem_base = smem_u32(smem);
    const int tid  = threadIdx.x;
    const int wid  = tid >> 5;
    const int lane = tid & 31;
    const int mm   = blockIdx.x & 31;
    const int q    = blockIdx.x >> 5;
    const int NT   = 16;                        // j tiles per CTA

    if (wid == 0) TCGEN05_ALLOC(smem_base + SMEM_CTRL, 512);
    if (tid == 0) {
        MBARRIER_INIT(BAR(0), 1);                                   // a_full
        MBARRIER_INIT(BAR(1), 1); MBARRIER_INIT(BAR(2), 1); MBARRIER_INIT(BAR(3), 1); // b_full
        MBARRIER_INIT(BAR(4), 1); MBARRIER_INIT(BAR(5), 1); MBARRIER_INIT(BAR(6), 1); // hdone
        MBARRIER_INIT(BAR(7), NEPI); MBARRIER_INIT(BAR(8), NEPI);   // d_free (16 warps)
    }
    __syncthreads();
    uint32_t tmem_base;
    asm volatile("ld.shared.b32 %0, [%1];" : "=r"(tmem_base) : "r"(smem_base + SMEM_CTRL));

    if (tid == 17 * 32) {
        // ---- TMA producer warp ----
        MBARRIER_EXPECT_TX(BAR(0), 2 * TILE_BYTES);
        bulk_copy(smem_base + SMEM_A, g_zswz + (size_t)(2 * mm) * TILE_BYTES,
                  2 * TILE_BYTES, BAR(0));
        for (int H = 0; H < 2 * NT; ++H) produce_half(H, q, smem_base);
    }
    if (tid == 16 * 32) {
        // ---- MMA issuer warp ----
        MBARRIER_WAIT_PARITY(BAR(0), 0);        // A resident
        for (int H = 0; H < 2 * NT; ++H) issue_half(H, smem_base, tmem_base);
    }

    // ---- epilogue warps (0-15) ----
    const int sub     = wid & 3;                // TMEM subpartition (lane group)
    const int chunk   = wid >> 2;               // 32-col chunk (0..3)
    const int rrow    = sub * 32 + lane;
    const int colbase = chunk * 32;
    const int gbase   = mm * 256;
    float acc[2][4] = {{0.f,0.f,0.f,0.f},{0.f,0.f,0.f,0.f}};

    if (wid < NEPI) {
        const int tA0 = 2 * mm, tA1 = 2 * mm + 1;
        const int pA0 = tA0 ^ 32, pA1 = tA1 ^ 32;
        const int gi0 = gbase + rrow, gi1 = gbase + 128 + rrow;
        for (int l = 0; l < NT; ++l) {
            const int p = l & 1;
            const int jt = q * 16 + l;

            // wait for tile l's MMAs (hdone of its second half)
            const int H2 = 2 * l + 1;
            MBARRIER_WAIT_PARITY(BAR(4 + H2 % 3), (H2 / 3) & 1);
            TCGEN05_FENCE_AFTER();

            // f16 D: region a at word offset (p*2+a)*64; warp's 32 cols = 16 words
            const uint32_t t0 = tmem_base + (p * 2) * 64 + chunk * 16
                              + ((uint32_t)sub << 21);
            const uint32_t t1 = t0 + 64;
            const uint32_t db = BAR(7 + p);

            if (jt == tA0)      epi_tile<1,0>(t0, t1, colbase, rrow, gi0, gi1, db, lane, acc);
            else if (jt == tA1) epi_tile<0,1>(t0, t1, colbase, rrow, gi0, gi1, db, lane, acc);
            else if (jt == pA0) epi_tile<2,0>(t0, t1, colbase, rrow, gi0, gi1, db, lane, acc);
            else if (jt == pA1) epi_tile<0,2>(t0, t1, colbase, rrow, gi0, gi1, db, lane, acc);
            else                epi_tile<0,0>(t0, t1, colbase, rrow, gi0, gi1, db, lane, acc);
        }
    }

    // --- combine per-chunk partials per row, store ---
    // (sred aliases the B ring; all B consumption finished before this point)
    __syncthreads();
    float* sred = reinterpret_cast<float*>(smem + SMEM_SRED);
    if (wid < NEPI) {
        sred[chunk * 256 + 0   + rrow] = (acc[0][0] + acc[0][1]) + (acc[0][2] + acc[0][3]);
        sred[chunk * 256 + 128 + rrow] = (acc[1][0] + acc[1][1]) + (acc[1][2] + acc[1][3]);
    }
    __syncthreads();
    if (tid < 256) g_ps[q][gbase + tid] =
        (sred[tid] + sred[256 + tid]) + (sred[512 + tid] + sred[768 + tid]);

    __syncthreads();
    if (wid == 0) { TCGEN05_RELINQ(); TCGEN05_DEALLOC(tmem_base, 512); }

    // --- last-CTA final reduction: loss_i = 2 + ln(S_i) - 2*posd_i; mean ---
    __shared__ unsigned int s_last;
    if (tid == 0) {
        __threadfence();                         // release all this CTA's writes
        s_last = (atomicAdd(&g_ctr, 1u) == 127u) ? 1u : 0u;
    }
    __syncthreads();
    if (s_last) {
        __threadfence();                         // acquire other CTAs' writes
        const float LN2 = 0.6931471805599453f;
        if (tid < 256) {
            float s = 0.0f;
            for (int i = tid; i < N_ROWS; i += 256) {
                float S = (__ldcg(&g_ps[0][i]) + __ldcg(&g_ps[1][i]))
                        + (__ldcg(&g_ps[2][i]) + __ldcg(&g_ps[3][i]));
                s += fmaf(fast_lg2(S), LN2, 2.0f - 2.0f * __ldcg(&g_posd[i]));
            }
            sred[tid] = s;
        }
        __syncthreads();
        #pragma unroll
        for (int o = 128; o; o >>= 1) {
            if (tid < o) sred[tid] += sred[tid + o];
            __syncthreads();
        }
        if (tid == 0) {
            out[0] = sred[0] / (float)N_ROWS;
            g_ctr = 0u;                          // reset for next graph replay
        }
    }
#endif // TC_ENABLED
}

// ---------------------------------------------------------------------------
extern "C" void kernel_launch(void* const* d_in, const int* in_sizes, int n_in,
                              void* d_out, int out_size) {
    const float* zi = (const float*)d_in[0];
    const float* zj = (const float*)d_in[1];
    float* out = (float*)d_out;

    cudaFuncSetAttribute(gemm_lse_kernel,
                         cudaFuncAttributeMaxDynamicSharedMemorySize, SMEM_TOTAL);

    prep_kernel<<<512, 256>>>(zi, zj);
    gemm_lse_kernel<<<128, THREADS, SMEM_TOTAL>>>(out);
}